// round 9
// baseline (speedup 1.0000x reference)
#include <cuda_runtime.h>
#include <math.h>

#define BB 32768
#define EE 9
#define RANKK 50
#define DD 450            // E*RANK
#define WPB 8             // warps per block
#define NB 592            // persistent grid: 148 SMs x 4 blocks
#define NBP 608           // padded partial stride (pad slots stay zero)
#define TOTW (NB * WPB)   // 4736 warps
#define XOFF 2            // head starts at sxw[2] so rel (sxw[452]) is 16B-aligned
#define XSZ 1352          // 2 + 450 + 900

// per-block partials: [v*NBP + block], v = 0..8 load, 9..17 importance
__device__ float g_part[18 * NBP];
__device__ unsigned int g_count = 0;

__device__ __forceinline__ float softplusf(float x) {
    if (x > 20.0f) return x;
    return log1pf(expf(x));
}
__device__ __forceinline__ float phif(float z) {
    return 0.5f * (1.0f + erff(z * 0.70710678118654752f));
}
__device__ __forceinline__ void cp_async8(unsigned int dst, const void* src) {
    asm volatile("cp.async.ca.shared.global [%0], [%1], 8;" :: "r"(dst), "l"(src));
}
__device__ __forceinline__ void cp_async16(unsigned int dst, const void* src) {
    asm volatile("cp.async.ca.shared.global [%0], [%1], 16;" :: "r"(dst), "l"(src));
}
__device__ __forceinline__ void cp_async_wait_all() {
    asm volatile("cp.async.commit_group;\n\tcp.async.wait_group 0;" ::: "memory");
}
__device__ __forceinline__ void prefetch_l2(const void* p) {
    asm volatile("prefetch.global.L2 [%0];" :: "l"(p));
}

__global__ __launch_bounds__(256, 4) void swise_main_kernel(
    const int* __restrict__ queries, const int* __restrict__ these_queries,
    const float* __restrict__ entity, const float* __restrict__ rel,
    const float* __restrict__ rel_diag,
    const float* __restrict__ bh, const float* __restrict__ bt,
    const float* __restrict__ c_param,
    const float* __restrict__ cnn_w, const float* __restrict__ cnn_b,
    const float* __restrict__ h2e_w, const float* __restrict__ h2e_b,
    const float* __restrict__ cnnn_w, const float* __restrict__ cnnn_b,
    const float* __restrict__ h2en_w, const float* __restrict__ h2en_b,
    const float* __restrict__ noise, float* __restrict__ y_out, int loss_idx)
{
    __shared__ __align__(16) float sx[WPB][XSZ];   // x image per warp, contiguous
    __shared__ float swc[25], swn[25];
    __shared__ __align__(16) float sh2e[EE * 128];
    __shared__ __align__(16) float sh2en[EE * 128];
    __shared__ float sbc[2];
    __shared__ float sbe[EE], sben[EE];
    __shared__ float s_load[EE], s_imp[EE];
    __shared__ unsigned int s_is_last;
    __shared__ double totals[18];

    const int tid = threadIdx.x;
    for (int i = tid; i < 25; i += blockDim.x) { swc[i] = cnn_w[i]; swn[i] = cnnn_w[i]; }
    for (int i = tid; i < EE * 128; i += blockDim.x) { sh2e[i] = h2e_w[i]; sh2en[i] = h2en_w[i]; }
    if (tid == 0) { sbc[0] = cnn_b[0]; sbc[1] = cnnn_b[0]; }
    if (tid < EE) { sbe[tid] = h2e_b[tid]; sben[tid] = h2en_b[tid];
                    s_load[tid] = 0.0f; s_imp[tid] = 0.0f; }
    __syncthreads();

    const int warp = tid >> 5, lane = tid & 31;
    const int ly = lane >> 2;          // oh  (0..7)
    const int lx = lane & 3;           // ow group (0..3), ow = 4*lx + q
    float* sxw = sx[warp];
    const unsigned int sxw_u32 =
        (unsigned int)__cvta_generic_to_shared(sxw);
    const int gw = blockIdx.x * WPB + warp;

    for (int b = gw; b < BB; b += TOTW) {
        const int q0 = queries[3 * b];
        const int q1 = queries[3 * b + 1];
        const int t2 = these_queries[3 * b + 2];

        __syncwarp();   // WAR: previous iteration's reads of sxw done

        // ---- stage x = [head | rel] via cp.async (no register round-trip) ----
        const float2* hrow = (const float2*)(entity + (size_t)q0 * DD);
        const float4* rrow = (const float4*)(rel + (size_t)q1 * (2 * DD));
        #pragma unroll
        for (int t = 0; t < 7; t++) {
            const int i = lane + 32 * t;
            cp_async8(sxw_u32 + 4 * (XOFF + 2 * i), hrow + i);
            cp_async16(sxw_u32 + 4 * (XOFF + DD + 4 * i), rrow + i);
        }
        if (lane == 0) {    // i = 224 tail
            cp_async8(sxw_u32 + 4 * (XOFF + 2 * 224), hrow + 224);
            cp_async16(sxw_u32 + 4 * (XOFF + DD + 4 * 224), rrow + 224);
        }

        // ---- hoisted noise loads (latency overlapped with conv) ----
        float noiser[EE];
        #pragma unroll
        for (int e = 0; e < EE; e++)
            noiser[e] = __ldg(noise + (size_t)b * EE + e);

        // ---- prefetch next element's gather rows to L2 (hide DRAM misses) ----
        {
            const int bn = b + TOTW;
            if (bn < BB) {
                const char* hn = (const char*)(entity + (size_t)queries[3 * bn] * DD);
                const char* rn = (const char*)(rel + (size_t)queries[3 * bn + 1] * (2 * DD));
                const char* tn = (const char*)(entity + (size_t)these_queries[3 * bn + 2] * DD);
                // 59 lines: head 15 (L<15), rel 29 (15<=L<44), tail 15 (44<=L<59)
                const int L0 = lane;
                const char* p0 = (L0 < 15) ? (hn + 128 * L0)
                               : (L0 < 44) ? (rn + 128 * (L0 - 15))
                                           : (tn + 128 * (L0 - 44));
                prefetch_l2(p0);
                const int L1 = 32 + lane;
                if (L1 < 59) {
                    const char* p1 = (L1 < 44) ? (rn + 128 * (L1 - 15))
                                               : (tn + 128 * (L1 - 44));
                    prefetch_l2(p1);
                }
            }
        }
        cp_async_wait_all();
        __syncwarp();

        // ---- conv (stride 3, VALID): each lane computes 4 consecutive ow ----
        float accc[4] = {0.f, 0.f, 0.f, 0.f};
        float accn[4] = {0.f, 0.f, 0.f, 0.f};
        #pragma unroll
        for (int kh = 0; kh < 5; kh++) {
            const float* rp = sxw + XOFF + (3 * ly + kh) * RANKK + 12 * lx;
            float row[14];
            #pragma unroll
            for (int j2 = 0; j2 < 7; j2++) {
                const float2 t = *(const float2*)(rp + 2 * j2);
                row[2 * j2] = t.x; row[2 * j2 + 1] = t.y;
            }
            #pragma unroll
            for (int kw = 0; kw < 5; kw++) {
                const float wc = swc[kh * 5 + kw], wn = swn[kh * 5 + kw];
                #pragma unroll
                for (int q = 0; q < 4; q++) {
                    const float xv = row[3 * q + kw];
                    accc[q] = fmaf(xv, wc, accc[q]);
                    accn[q] = fmaf(xv, wn, accn[q]);
                }
            }
        }
        #pragma unroll
        for (int q = 0; q < 4; q++) { accc[q] += sbc[0]; accn[q] += sbc[1]; }

        // ---- fused linear: float4 weight loads, f_base = 16*ly + 4*lx ----
        const int f_base = 16 * ly + 4 * lx;
        float clean[EE], stdv[EE];
        #pragma unroll
        for (int e = 0; e < EE; e++) {
            const float4 wc4 = *(const float4*)&sh2e[e * 128 + f_base];
            const float4 wn4 = *(const float4*)&sh2en[e * 128 + f_base];
            float c0 = accc[0] * wc4.x; c0 = fmaf(accc[1], wc4.y, c0);
            c0 = fmaf(accc[2], wc4.z, c0); c0 = fmaf(accc[3], wc4.w, c0);
            float n0 = accn[0] * wn4.x; n0 = fmaf(accn[1], wn4.y, n0);
            n0 = fmaf(accn[2], wn4.z, n0); n0 = fmaf(accn[3], wn4.w, n0);
            clean[e] = c0; stdv[e] = n0;
        }
        // ---- split butterfly: round 1 routes clean->lanes<16, stdv->lanes>=16 ----
        const bool lowh = (lane < 16);
        float val[EE];
        #pragma unroll
        for (int e = 0; e < EE; e++) {
            const float oc = __shfl_xor_sync(0xffffffffu, clean[e], 16);
            const float os = __shfl_xor_sync(0xffffffffu, stdv[e], 16);
            val[e] = lowh ? (clean[e] + oc) : (stdv[e] + os);
        }
        #pragma unroll
        for (int off = 8; off > 0; off >>= 1) {
            #pragma unroll
            for (int e = 0; e < EE; e++)
                val[e] += __shfl_xor_sync(0xffffffffu, val[e], off);
        }
        #pragma unroll
        for (int e = 0; e < EE; e++) {
            const float other = __shfl_xor_sync(0xffffffffu, val[e], 16);
            clean[e] = lowh ? val[e] : other;
            stdv[e]  = lowh ? other  : val[e];
        }

        // ---- gating (uniform across lanes) ----
        float noisyv[EE];
        #pragma unroll
        for (int e = 0; e < EE; e++) {
            clean[e] += sbe[e];
            stdv[e] = softplusf(stdv[e] + sben[e]) + 0.01f;
            noisyv[e] = fmaf(noiser[e], stdv[e], clean[e]);
        }
        int i1 = 0; float v1 = noisyv[0];
        #pragma unroll
        for (int e = 1; e < EE; e++) if (noisyv[e] > v1) { v1 = noisyv[e]; i1 = e; }
        int i2 = -1; float v2 = -INFINITY;
        #pragma unroll
        for (int e = 0; e < EE; e++) if (e != i1 && noisyv[e] > v2) { v2 = noisyv[e]; i2 = e; }
        float v3 = -INFINITY;
        #pragma unroll
        for (int e = 0; e < EE; e++) if (e != i1 && e != i2 && noisyv[e] > v3) v3 = noisyv[e];

        const float t_e = expf(v2 - v1);
        const float g1 = 1.0f / (1.0f + t_e);
        const float g2 = t_e / (1.0f + t_e);

        // prob/load: one expert per lane (parallel erf, conflict-free atomics)
        if (lane < EE) {
            float ce = 0.0f, se = 1.0f, ne = 0.0f;
            #pragma unroll
            for (int e = 0; e < EE; e++)
                if (lane == e) { ce = clean[e]; se = stdv[e]; ne = noisyv[e]; }
            const float thr = (ne > v3) ? v3 : v2;
            atomicAdd(&s_load[lane], phif((ce - thr) / se));
        }
        if (lane == 0) {
            atomicAdd(&s_imp[i1], g1);
            if (g2 > 0.0f) atomicAdd(&s_imp[i2], g2);
        }

        // ---- Givens + distance, ONLY for experts i1 and i2 (50 pairs) ----
        const float* rd = rel_diag + (size_t)q1 * DD;
        const float* rh = entity + (size_t)t2 * DD;
        float dA = 0.0f, dB = 0.0f;    // d2[i1], d2[i2]

        {   // item 1: lanes 0..24 -> expert i1, lanes 25..31 -> expert i2
            const bool sel = lane < 25;
            const int e = sel ? i1 : i2;
            const int p = sel ? lane : lane - 25;
            const float2 r2 = __ldg((const float2*)(rd + e * RANKK) + p);
            const float2 h2v = __ldg((const float2*)(rh + e * RANKK) + p);
            const float inv = rsqrtf(fmaxf(r2.x * r2.x + r2.y * r2.y, 1e-30f));
            const float c0 = r2.x * inv, c1 = r2.y * inv;
            const float x0 = sxw[XOFF + e * RANKK + 2 * p];
            const float x1 = sxw[XOFF + e * RANKK + 2 * p + 1];
            const float rl0 = sxw[XOFF + DD + e * (2 * RANKK) + 2 * p];
            const float rl1 = sxw[XOFF + DD + e * (2 * RANKK) + 2 * p + 1];
            const float u0 = (c0 * x0 - c1 * x1) + rl0 - h2v.x;
            const float u1 = (c1 * x0 + c0 * x1) + rl1 - h2v.y;
            const float dd = fmaf(u0, u0, u1 * u1);
            if (sel) dA += dd; else dB += dd;
        }
        if (lane < 18) {  // item 2: expert i2, p = lane+7
            const int p = lane + 7;
            const int e = i2;
            const float2 r2 = __ldg((const float2*)(rd + e * RANKK) + p);
            const float2 h2v = __ldg((const float2*)(rh + e * RANKK) + p);
            const float inv = rsqrtf(fmaxf(r2.x * r2.x + r2.y * r2.y, 1e-30f));
            const float c0 = r2.x * inv, c1 = r2.y * inv;
            const float x0 = sxw[XOFF + e * RANKK + 2 * p];
            const float x1 = sxw[XOFF + e * RANKK + 2 * p + 1];
            const float rl0 = sxw[XOFF + DD + e * (2 * RANKK) + 2 * p];
            const float rl1 = sxw[XOFF + DD + e * (2 * RANKK) + 2 * p + 1];
            const float u0 = (c0 * x0 - c1 * x1) + rl0 - h2v.x;
            const float u1 = (c1 * x0 + c0 * x1) + rl1 - h2v.y;
            dB = fmaf(u0, u0, fmaf(u1, u1, dB));
        }
        #pragma unroll
        for (int off = 16; off > 0; off >>= 1) {
            dA += __shfl_xor_sync(0xffffffffu, dA, off);
            dB += __shfl_xor_sync(0xffffffffu, dB, off);
        }

        // ---- score + masked logsumexp (mask = top-2 gates > 0) ----
        if (lane == 0) {
            const float cc = softplusf(c_param[q1]);
            const float bsum = bh[q0] + bt[t2];
            const float sc1 = bsum - cc * dA;
            const float sc2 = bsum - cc * dB;
            float s = expf(sc1) + (g2 > 0.0f ? expf(sc2) : 0.0f);
            if (s == 0.0f) s = 2.220446049250313e-16f;
            y_out[b] = logf(s);
        }
    }

    __syncthreads();
    if (tid < EE)       g_part[tid * NBP + blockIdx.x] = s_load[tid];
    else if (tid < 18)  g_part[tid * NBP + blockIdx.x] = s_imp[tid - 9];
    __threadfence();
    if (tid == 0) {
        const unsigned int c = atomicAdd(&g_count, 1u);
        s_is_last = (c == NB - 1) ? 1u : 0u;
    }
    __syncthreads();
    if (!s_is_last) return;

    // ---- last block: reduce 18 per-block partial vectors and emit loss ----
    for (int v = warp; v < 18; v += WPB) {
        float acc = 0.0f;
        #pragma unroll
        for (int j = 0; j < NBP / 32; j++)    // pads are zero
            acc += g_part[v * NBP + j * 32 + lane];
        #pragma unroll
        for (int off = 16; off > 0; off >>= 1)
            acc += __shfl_xor_sync(0xffffffffu, acc, off);
        if (lane == 0) totals[v] = (double)acc;
    }
    __syncthreads();
    if (tid == 0) {
        double ml = 0.0, mi = 0.0;
        for (int e = 0; e < EE; e++) { ml += totals[e]; mi += totals[9 + e]; }
        ml /= (double)EE; mi /= (double)EE;
        double vl = 0.0, vi = 0.0;
        for (int e = 0; e < EE; e++) {
            const double dl = totals[e] - ml;     vl += dl * dl;
            const double di = totals[9 + e] - mi; vi += di * di;
        }
        vl /= (double)(EE - 1); vi /= (double)(EE - 1);
        const double cvl = vl / (ml * ml + 1e-10);
        const double cvi = vi / (mi * mi + 1e-10);
        y_out[loss_idx] = (float)(0.01 * (cvi + cvl));
        g_count = 0;   // reset for next graph replay (deterministic)
    }
}

extern "C" void kernel_launch(void* const* d_in, const int* in_sizes, int n_in,
                              void* d_out, int out_size) {
    const int*   queries       = (const int*)  d_in[0];
    const int*   these_queries = (const int*)  d_in[1];
    const float* entity        = (const float*)d_in[2];
    const float* rel           = (const float*)d_in[3];
    const float* rel_diag      = (const float*)d_in[4];
    const float* bh            = (const float*)d_in[5];
    const float* bt            = (const float*)d_in[6];
    const float* c_param       = (const float*)d_in[7];
    const float* cnn_w         = (const float*)d_in[8];
    const float* cnn_b         = (const float*)d_in[9];
    const float* h2e_w         = (const float*)d_in[10];
    const float* h2e_b         = (const float*)d_in[11];
    const float* cnnn_w        = (const float*)d_in[12];
    const float* cnnn_b        = (const float*)d_in[13];
    const float* h2en_w        = (const float*)d_in[14];
    const float* h2en_b        = (const float*)d_in[15];
    const float* noise         = (const float*)d_in[16];
    float* out = (float*)d_out;

    swise_main_kernel<<<NB, 256>>>(
        queries, these_queries, entity, rel, rel_diag, bh, bt, c_param,
        cnn_w, cnn_b, h2e_w, h2e_b, cnnn_w, cnnn_b, h2en_w, h2en_b,
        noise, out, out_size - 1);
}

// round 10
// speedup vs baseline: 1.0541x; 1.0541x over previous
#include <cuda_runtime.h>
#include <math.h>

#define BB 32768
#define EE 9
#define RANKK 50
#define DD 450            // E*RANK
#define WPB 8             // warps per block
#define NB 740            // persistent grid: 148 SMs x 5 blocks
#define NBP 768           // padded partial stride (pad slots stay zero)
#define TOTW (NB * WPB)   // 5920 warps
#define XOFF 2            // head starts at sxw[2] so rel (sxw[452]) is 16B-aligned
#define XSZ 1352          // 2 + 450 + 900

// per-block partials: [v*NBP + block], v = 0..8 load, 9..17 importance
__device__ float g_part[18 * NBP];
__device__ unsigned int g_count = 0;

__device__ __forceinline__ float softplusf(float x) {
    if (x > 20.0f) return x;
    return log1pf(expf(x));
}
__device__ __forceinline__ float phif(float z) {
    return 0.5f * (1.0f + erff(z * 0.70710678118654752f));
}
__device__ __forceinline__ void cp_async8(unsigned int dst, const void* src) {
    asm volatile("cp.async.ca.shared.global [%0], [%1], 8;" :: "r"(dst), "l"(src));
}
__device__ __forceinline__ void cp_async16(unsigned int dst, const void* src) {
    asm volatile("cp.async.ca.shared.global [%0], [%1], 16;" :: "r"(dst), "l"(src));
}
__device__ __forceinline__ void cp_async_wait_all() {
    asm volatile("cp.async.commit_group;\n\tcp.async.wait_group 0;" ::: "memory");
}

__global__ __launch_bounds__(256, 5) void swise_main_kernel(
    const int* __restrict__ queries, const int* __restrict__ these_queries,
    const float* __restrict__ entity, const float* __restrict__ rel,
    const float* __restrict__ rel_diag,
    const float* __restrict__ bh, const float* __restrict__ bt,
    const float* __restrict__ c_param,
    const float* __restrict__ cnn_w, const float* __restrict__ cnn_b,
    const float* __restrict__ h2e_w, const float* __restrict__ h2e_b,
    const float* __restrict__ cnnn_w, const float* __restrict__ cnnn_b,
    const float* __restrict__ h2en_w, const float* __restrict__ h2en_b,
    const float* __restrict__ noise, float* __restrict__ y_out, int loss_idx)
{
    __shared__ __align__(16) float sx[WPB][XSZ];   // x image per warp, contiguous
    __shared__ float swc[25], swn[25];
    __shared__ float sbc[2];
    __shared__ float sbe[EE], sben[EE];
    __shared__ float s_load[EE], s_imp[EE];
    __shared__ unsigned int s_is_last;
    __shared__ double totals[18];

    const int tid = threadIdx.x;
    for (int i = tid; i < 25; i += blockDim.x) { swc[i] = cnn_w[i]; swn[i] = cnnn_w[i]; }
    if (tid == 0) { sbc[0] = cnn_b[0]; sbc[1] = cnnn_b[0]; }
    if (tid < EE) { sbe[tid] = h2e_b[tid]; sben[tid] = h2en_b[tid];
                    s_load[tid] = 0.0f; s_imp[tid] = 0.0f; }
    __syncthreads();

    const int warp = tid >> 5, lane = tid & 31;
    const int ly = lane >> 2;          // oh  (0..7)
    const int lx = lane & 3;           // ow group (0..3), ow = 4*lx + q
    const int f4 = (16 * ly + 4 * lx) >> 2;   // float4 index into weight rows
    float* sxw = sx[warp];
    const unsigned int sxw_u32 =
        (unsigned int)__cvta_generic_to_shared(sxw);
    const float4* wc4p = (const float4*)h2e_w;    // [EE*32] float4, L1-hot
    const float4* wn4p = (const float4*)h2en_w;
    const int gw = blockIdx.x * WPB + warp;

    for (int b = gw; b < BB; b += TOTW) {
        const int q0 = queries[3 * b];
        const int q1 = queries[3 * b + 1];
        const int t2 = these_queries[3 * b + 2];

        __syncwarp();   // WAR: previous iteration's reads of sxw done

        // ---- stage x = [head | rel] via cp.async (no register round-trip) ----
        const float2* hrow = (const float2*)(entity + (size_t)q0 * DD);
        const float4* rrow = (const float4*)(rel + (size_t)q1 * (2 * DD));
        #pragma unroll
        for (int t = 0; t < 7; t++) {
            const int i = lane + 32 * t;
            cp_async8(sxw_u32 + 4 * (XOFF + 2 * i), hrow + i);
            cp_async16(sxw_u32 + 4 * (XOFF + DD + 4 * i), rrow + i);
        }
        if (lane == 0) {    // i = 224 tail
            cp_async8(sxw_u32 + 4 * (XOFF + 2 * 224), hrow + 224);
            cp_async16(sxw_u32 + 4 * (XOFF + DD + 4 * 224), rrow + 224);
        }

        // ---- hoisted noise loads (latency overlapped with staging wait) ----
        float noiser[EE];
        #pragma unroll
        for (int e = 0; e < EE; e++)
            noiser[e] = __ldg(noise + (size_t)b * EE + e);

        cp_async_wait_all();
        __syncwarp();

        // ---- conv (stride 3, VALID): each lane computes 4 consecutive ow ----
        float accc[4] = {0.f, 0.f, 0.f, 0.f};
        float accn[4] = {0.f, 0.f, 0.f, 0.f};
        #pragma unroll
        for (int kh = 0; kh < 5; kh++) {
            const float* rp = sxw + XOFF + (3 * ly + kh) * RANKK + 12 * lx;
            float row[14];
            #pragma unroll
            for (int j2 = 0; j2 < 7; j2++) {
                const float2 t = *(const float2*)(rp + 2 * j2);
                row[2 * j2] = t.x; row[2 * j2 + 1] = t.y;
            }
            #pragma unroll
            for (int kw = 0; kw < 5; kw++) {
                const float wc = swc[kh * 5 + kw], wn = swn[kh * 5 + kw];
                #pragma unroll
                for (int q = 0; q < 4; q++) {
                    const float xv = row[3 * q + kw];
                    accc[q] = fmaf(xv, wc, accc[q]);
                    accn[q] = fmaf(xv, wn, accn[q]);
                }
            }
        }
        #pragma unroll
        for (int q = 0; q < 4; q++) { accc[q] += sbc[0]; accn[q] += sbc[1]; }

        // ---- fused linear: weights via __ldg (L1-resident), float4 loads ----
        float clean[EE], stdv[EE];
        #pragma unroll
        for (int e = 0; e < EE; e++) {
            const float4 wc4 = __ldg(wc4p + e * 32 + f4);
            const float4 wn4 = __ldg(wn4p + e * 32 + f4);
            float c0 = accc[0] * wc4.x; c0 = fmaf(accc[1], wc4.y, c0);
            c0 = fmaf(accc[2], wc4.z, c0); c0 = fmaf(accc[3], wc4.w, c0);
            float n0 = accn[0] * wn4.x; n0 = fmaf(accn[1], wn4.y, n0);
            n0 = fmaf(accn[2], wn4.z, n0); n0 = fmaf(accn[3], wn4.w, n0);
            clean[e] = c0; stdv[e] = n0;
        }
        // ---- split butterfly: round 1 routes clean->lanes<16, stdv->lanes>=16 ----
        const bool lowh = (lane < 16);
        float val[EE];
        #pragma unroll
        for (int e = 0; e < EE; e++) {
            const float oc = __shfl_xor_sync(0xffffffffu, clean[e], 16);
            const float os = __shfl_xor_sync(0xffffffffu, stdv[e], 16);
            val[e] = lowh ? (clean[e] + oc) : (stdv[e] + os);
        }
        #pragma unroll
        for (int off = 8; off > 0; off >>= 1) {
            #pragma unroll
            for (int e = 0; e < EE; e++)
                val[e] += __shfl_xor_sync(0xffffffffu, val[e], off);
        }
        #pragma unroll
        for (int e = 0; e < EE; e++) {
            const float other = __shfl_xor_sync(0xffffffffu, val[e], 16);
            clean[e] = lowh ? val[e] : other;
            stdv[e]  = lowh ? other  : val[e];
        }

        // ---- gating (uniform across lanes) ----
        float noisyv[EE];
        #pragma unroll
        for (int e = 0; e < EE; e++) {
            clean[e] += sbe[e];
            stdv[e] = softplusf(stdv[e] + sben[e]) + 0.01f;
            noisyv[e] = fmaf(noiser[e], stdv[e], clean[e]);
        }
        int i1 = 0; float v1 = noisyv[0];
        #pragma unroll
        for (int e = 1; e < EE; e++) if (noisyv[e] > v1) { v1 = noisyv[e]; i1 = e; }
        int i2 = -1; float v2 = -INFINITY;
        #pragma unroll
        for (int e = 0; e < EE; e++) if (e != i1 && noisyv[e] > v2) { v2 = noisyv[e]; i2 = e; }
        float v3 = -INFINITY;
        #pragma unroll
        for (int e = 0; e < EE; e++) if (e != i1 && e != i2 && noisyv[e] > v3) v3 = noisyv[e];

        const float t_e = expf(v2 - v1);
        const float g1 = 1.0f / (1.0f + t_e);
        const float g2 = t_e / (1.0f + t_e);

        // prob/load: one expert per lane (parallel erf, conflict-free atomics)
        if (lane < EE) {
            float ce = 0.0f, se = 1.0f, ne = 0.0f;
            #pragma unroll
            for (int e = 0; e < EE; e++)
                if (lane == e) { ce = clean[e]; se = stdv[e]; ne = noisyv[e]; }
            const float thr = (ne > v3) ? v3 : v2;
            atomicAdd(&s_load[lane], phif((ce - thr) / se));
        }
        if (lane == 0) {
            atomicAdd(&s_imp[i1], g1);
            if (g2 > 0.0f) atomicAdd(&s_imp[i2], g2);
        }

        // ---- Givens + distance, ONLY for experts i1 and i2 (50 pairs) ----
        const float* rd = rel_diag + (size_t)q1 * DD;
        const float* rh = entity + (size_t)t2 * DD;
        float dA = 0.0f, dB = 0.0f;    // d2[i1], d2[i2]

        {   // item 1: lanes 0..24 -> expert i1, lanes 25..31 -> expert i2
            const bool sel = lane < 25;
            const int e = sel ? i1 : i2;
            const int p = sel ? lane : lane - 25;
            const float2 r2 = __ldg((const float2*)(rd + e * RANKK) + p);
            const float2 h2v = __ldg((const float2*)(rh + e * RANKK) + p);
            const float inv = rsqrtf(fmaxf(r2.x * r2.x + r2.y * r2.y, 1e-30f));
            const float c0 = r2.x * inv, c1 = r2.y * inv;
            const float x0 = sxw[XOFF + e * RANKK + 2 * p];
            const float x1 = sxw[XOFF + e * RANKK + 2 * p + 1];
            const float rl0 = sxw[XOFF + DD + e * (2 * RANKK) + 2 * p];
            const float rl1 = sxw[XOFF + DD + e * (2 * RANKK) + 2 * p + 1];
            const float u0 = (c0 * x0 - c1 * x1) + rl0 - h2v.x;
            const float u1 = (c1 * x0 + c0 * x1) + rl1 - h2v.y;
            const float dd = fmaf(u0, u0, u1 * u1);
            if (sel) dA += dd; else dB += dd;
        }
        if (lane < 18) {  // item 2: expert i2, p = lane+7
            const int p = lane + 7;
            const int e = i2;
            const float2 r2 = __ldg((const float2*)(rd + e * RANKK) + p);
            const float2 h2v = __ldg((const float2*)(rh + e * RANKK) + p);
            const float inv = rsqrtf(fmaxf(r2.x * r2.x + r2.y * r2.y, 1e-30f));
            const float c0 = r2.x * inv, c1 = r2.y * inv;
            const float x0 = sxw[XOFF + e * RANKK + 2 * p];
            const float x1 = sxw[XOFF + e * RANKK + 2 * p + 1];
            const float rl0 = sxw[XOFF + DD + e * (2 * RANKK) + 2 * p];
            const float rl1 = sxw[XOFF + DD + e * (2 * RANKK) + 2 * p + 1];
            const float u0 = (c0 * x0 - c1 * x1) + rl0 - h2v.x;
            const float u1 = (c1 * x0 + c0 * x1) + rl1 - h2v.y;
            dB = fmaf(u0, u0, fmaf(u1, u1, dB));
        }
        #pragma unroll
        for (int off = 16; off > 0; off >>= 1) {
            dA += __shfl_xor_sync(0xffffffffu, dA, off);
            dB += __shfl_xor_sync(0xffffffffu, dB, off);
        }

        // ---- score + masked logsumexp (mask = top-2 gates > 0) ----
        if (lane == 0) {
            const float cc = softplusf(c_param[q1]);
            const float bsum = bh[q0] + bt[t2];
            const float sc1 = bsum - cc * dA;
            const float sc2 = bsum - cc * dB;
            float s = expf(sc1) + (g2 > 0.0f ? expf(sc2) : 0.0f);
            if (s == 0.0f) s = 2.220446049250313e-16f;
            y_out[b] = logf(s);
        }
    }

    __syncthreads();
    if (tid < EE)       g_part[tid * NBP + blockIdx.x] = s_load[tid];
    else if (tid < 18)  g_part[tid * NBP + blockIdx.x] = s_imp[tid - 9];
    __threadfence();
    if (tid == 0) {
        const unsigned int c = atomicAdd(&g_count, 1u);
        s_is_last = (c == NB - 1) ? 1u : 0u;
    }
    __syncthreads();
    if (!s_is_last) return;

    // ---- last block: reduce 18 per-block partial vectors and emit loss ----
    for (int v = warp; v < 18; v += WPB) {
        float acc = 0.0f;
        #pragma unroll
        for (int j = 0; j < NBP / 32; j++)    // pads are zero
            acc += g_part[v * NBP + j * 32 + lane];
        #pragma unroll
        for (int off = 16; off > 0; off >>= 1)
            acc += __shfl_xor_sync(0xffffffffu, acc, off);
        if (lane == 0) totals[v] = (double)acc;
    }
    __syncthreads();
    if (tid == 0) {
        double ml = 0.0, mi = 0.0;
        for (int e = 0; e < EE; e++) { ml += totals[e]; mi += totals[9 + e]; }
        ml /= (double)EE; mi /= (double)EE;
        double vl = 0.0, vi = 0.0;
        for (int e = 0; e < EE; e++) {
            const double dl = totals[e] - ml;     vl += dl * dl;
            const double di = totals[9 + e] - mi; vi += di * di;
        }
        vl /= (double)(EE - 1); vi /= (double)(EE - 1);
        const double cvl = vl / (ml * ml + 1e-10);
        const double cvi = vi / (mi * mi + 1e-10);
        y_out[loss_idx] = (float)(0.01 * (cvi + cvl));
        g_count = 0;   // reset for next graph replay (deterministic)
    }
}

extern "C" void kernel_launch(void* const* d_in, const int* in_sizes, int n_in,
                              void* d_out, int out_size) {
    const int*   queries       = (const int*)  d_in[0];
    const int*   these_queries = (const int*)  d_in[1];
    const float* entity        = (const float*)d_in[2];
    const float* rel           = (const float*)d_in[3];
    const float* rel_diag      = (const float*)d_in[4];
    const float* bh            = (const float*)d_in[5];
    const float* bt            = (const float*)d_in[6];
    const float* c_param       = (const float*)d_in[7];
    const float* cnn_w         = (const float*)d_in[8];
    const float* cnn_b         = (const float*)d_in[9];
    const float* h2e_w         = (const float*)d_in[10];
    const float* h2e_b         = (const float*)d_in[11];
    const float* cnnn_w        = (const float*)d_in[12];
    const float* cnnn_b        = (const float*)d_in[13];
    const float* h2en_w        = (const float*)d_in[14];
    const float* h2en_b        = (const float*)d_in[15];
    const float* noise         = (const float*)d_in[16];
    float* out = (float*)d_out;

    swise_main_kernel<<<NB, 256>>>(
        queries, these_queries, entity, rel, rel_diag, bh, bt, c_param,
        cnn_w, cnn_b, h2e_w, h2e_b, cnnn_w, cnnn_b, h2en_w, h2en_b,
        noise, out, out_size - 1);
}

// round 11
// speedup vs baseline: 1.1760x; 1.1156x over previous
#include <cuda_runtime.h>
#include <math.h>

#define BB 32768
#define EE 9
#define RANKK 50
#define DD 450            // E*RANK
#define WPB 8             // warps per block
#define NB 740            // persistent grid: 148 SMs x 5 blocks
#define NBP 768           // padded partial stride (pad slots stay zero)
#define TOTW (NB * WPB)   // 5920 warps
#define XOFF 2            // head starts at sxw[2] so rel (sxw[452]) is 16B-aligned
#define XSZ 1352          // 2 + 450 + 900

// per-block partials: [v*NBP + block], v = 0..8 load, 9..17 importance
__device__ float g_part[18 * NBP];
__device__ unsigned int g_count = 0;

__device__ __forceinline__ float softplusf(float x) {
    if (x > 20.0f) return x;
    return log1pf(expf(x));
}
__device__ __forceinline__ float phif(float z) {
    return 0.5f * (1.0f + erff(z * 0.70710678118654752f));
}
__device__ __forceinline__ void cp_async8(unsigned int dst, const void* src) {
    asm volatile("cp.async.ca.shared.global [%0], [%1], 8;" :: "r"(dst), "l"(src));
}
__device__ __forceinline__ void cp_async16(unsigned int dst, const void* src) {
    asm volatile("cp.async.ca.shared.global [%0], [%1], 16;" :: "r"(dst), "l"(src));
}
__device__ __forceinline__ void cp_async_wait_all() {
    asm volatile("cp.async.commit_group;\n\tcp.async.wait_group 0;" ::: "memory");
}
// order-preserving float -> uint map (monotone): sort by unsigned compare
__device__ __forceinline__ unsigned int fmap(float f) {
    const unsigned int u = __float_as_uint(f);
    return (u & 0x80000000u) ? ~u : (u | 0x80000000u);
}
__device__ __forceinline__ float funmap(unsigned int m) {
    return (m & 0x80000000u) ? __uint_as_float(m & 0x7FFFFFFFu)
                             : __uint_as_float(~m);
}

__global__ __launch_bounds__(256, 5) void swise_main_kernel(
    const int* __restrict__ queries, const int* __restrict__ these_queries,
    const float* __restrict__ entity, const float* __restrict__ rel,
    const float* __restrict__ rel_diag,
    const float* __restrict__ bh, const float* __restrict__ bt,
    const float* __restrict__ c_param,
    const float* __restrict__ cnn_w, const float* __restrict__ cnn_b,
    const float* __restrict__ h2e_w, const float* __restrict__ h2e_b,
    const float* __restrict__ cnnn_w, const float* __restrict__ cnnn_b,
    const float* __restrict__ h2en_w, const float* __restrict__ h2en_b,
    const float* __restrict__ noise, float* __restrict__ y_out, int loss_idx)
{
    __shared__ __align__(16) float sx[WPB][XSZ];   // x image per warp, contiguous
    __shared__ float2 swcn[25];                    // interleaved conv weights
    __shared__ float sbc[2];
    __shared__ float sbeb[18];                     // [0..8]=h2e_b, [9..17]=h2en_b
    __shared__ float s_load[EE], s_imp[EE];
    __shared__ unsigned int s_is_last;
    __shared__ double totals[18];

    const int tid = threadIdx.x;
    for (int i = tid; i < 25; i += blockDim.x)
        swcn[i] = make_float2(cnn_w[i], cnnn_w[i]);
    if (tid == 0) { sbc[0] = cnn_b[0]; sbc[1] = cnnn_b[0]; }
    if (tid < EE) { sbeb[tid] = h2e_b[tid]; sbeb[9 + tid] = h2en_b[tid];
                    s_load[tid] = 0.0f; s_imp[tid] = 0.0f; }
    __syncthreads();

    const int warp = tid >> 5, lane = tid & 31;
    const int ly = lane >> 2;          // oh  (0..7)
    const int lx = lane & 3;           // ow group (0..3), ow = 4*lx + q
    const int f4 = (16 * ly + 4 * lx) >> 2;   // float4 index into weight rows
    const int k9 = lane & 15;          // expert key within each half-warp
    float* sxw = sx[warp];
    const unsigned int sxw_u32 =
        (unsigned int)__cvta_generic_to_shared(sxw);
    const float4* wc4p = (const float4*)h2e_w;    // [EE*32] float4, L1-hot
    const float4* wn4p = (const float4*)h2en_w;
    const int gw = blockIdx.x * WPB + warp;

    for (int b = gw; b < BB; b += TOTW) {
        const int q0 = queries[3 * b];
        const int q1 = queries[3 * b + 1];
        const int t2 = these_queries[3 * b + 2];

        __syncwarp();   // WAR: previous iteration's reads of sxw done

        // ---- stage x = [head | rel] via cp.async (no register round-trip) ----
        const float2* hrow = (const float2*)(entity + (size_t)q0 * DD);
        const float4* rrow = (const float4*)(rel + (size_t)q1 * (2 * DD));
        #pragma unroll
        for (int t = 0; t < 7; t++) {
            const int i = lane + 32 * t;
            cp_async8(sxw_u32 + 4 * (XOFF + 2 * i), hrow + i);
            cp_async16(sxw_u32 + 4 * (XOFF + DD + 4 * i), rrow + i);
        }
        if (lane == 0) {    // i = 224 tail
            cp_async8(sxw_u32 + 4 * (XOFF + 2 * 224), hrow + 224);
            cp_async16(sxw_u32 + 4 * (XOFF + DD + 4 * 224), rrow + 224);
        }

        // ---- hoisted noise load: lane e<9 owns expert e ----
        const float noise_e = (lane < EE)
            ? __ldg(noise + (size_t)b * EE + lane) : 0.0f;

        cp_async_wait_all();
        __syncwarp();

        // ---- conv (stride 3, VALID): each lane computes 4 consecutive ow ----
        float accc[4] = {0.f, 0.f, 0.f, 0.f};
        float accn[4] = {0.f, 0.f, 0.f, 0.f};
        #pragma unroll
        for (int kh = 0; kh < 5; kh++) {
            const float* rp = sxw + XOFF + (3 * ly + kh) * RANKK + 12 * lx;
            float row[14];
            #pragma unroll
            for (int j2 = 0; j2 < 7; j2++) {
                const float2 t = *(const float2*)(rp + 2 * j2);
                row[2 * j2] = t.x; row[2 * j2 + 1] = t.y;
            }
            #pragma unroll
            for (int kw = 0; kw < 5; kw++) {
                const float2 w2 = swcn[kh * 5 + kw];
                #pragma unroll
                for (int q = 0; q < 4; q++) {
                    const float xv = row[3 * q + kw];
                    accc[q] = fmaf(xv, w2.x, accc[q]);
                    accn[q] = fmaf(xv, w2.y, accn[q]);
                }
            }
        }
        #pragma unroll
        for (int q = 0; q < 4; q++) { accc[q] += sbc[0]; accn[q] += sbc[1]; }

        // ---- fused linear: weights via __ldg (L1-resident), float4 loads ----
        float clean[EE], stdv[EE];
        #pragma unroll
        for (int e = 0; e < EE; e++) {
            const float4 wc4 = __ldg(wc4p + e * 32 + f4);
            const float4 wn4 = __ldg(wn4p + e * 32 + f4);
            float c0 = accc[0] * wc4.x; c0 = fmaf(accc[1], wc4.y, c0);
            c0 = fmaf(accc[2], wc4.z, c0); c0 = fmaf(accc[3], wc4.w, c0);
            float n0 = accn[0] * wn4.x; n0 = fmaf(accn[1], wn4.y, n0);
            n0 = fmaf(accn[2], wn4.z, n0); n0 = fmaf(accn[3], wn4.w, n0);
            clean[e] = c0; stdv[e] = n0;
        }
        // ---- split butterfly: clean sums -> low half, stdv sums -> high half ----
        const bool lowh = (lane < 16);
        float val[EE];
        #pragma unroll
        for (int e = 0; e < EE; e++) {
            const float oc = __shfl_xor_sync(0xffffffffu, clean[e], 16);
            const float os = __shfl_xor_sync(0xffffffffu, stdv[e], 16);
            val[e] = lowh ? (clean[e] + oc) : (stdv[e] + os);
        }
        #pragma unroll
        for (int off = 8; off > 0; off >>= 1) {
            #pragma unroll
            for (int e = 0; e < EE; e++)
                val[e] += __shfl_xor_sync(0xffffffffu, val[e], off);
        }

        // ---- lane-parallel gating: lane e<9 owns expert e ----
        // low lane e picks clean[e]+bias; high lane 16+e picks stdvraw[e]+bias
        float picked = 0.0f;
        #pragma unroll
        for (int e = 0; e < EE; e++)
            if (k9 == e) picked = val[e];
        if (k9 < EE) picked += sbeb[(lowh ? 0 : 9) + k9];
        const float other = __shfl_xor_sync(0xffffffffu, picked, 16);

        float ce = 0.f, se = 1.f, ne = 0.f;
        unsigned int m1 = 0u;
        if (lane < EE) {
            ce = picked;
            se = softplusf(other) + 0.01f;
            ne = fmaf(noise_e, se, ce);
            m1 = fmap(ne);
        }
        // top-3 via integer redux + ballot (first-index tie-break)
        const unsigned int M1 = __reduce_max_sync(0xffffffffu, m1);
        const int i1 = __ffs(__ballot_sync(0xffffffffu, m1 == M1 && lane < EE)) - 1;
        const unsigned int m2 = (lane == i1) ? 0u : m1;
        const unsigned int M2 = __reduce_max_sync(0xffffffffu, m2);
        const int i2 = __ffs(__ballot_sync(0xffffffffu, m2 == M2 && lane < EE && lane != i1)) - 1;
        const unsigned int m3 = (lane == i2) ? 0u : m2;
        const unsigned int M3 = __reduce_max_sync(0xffffffffu, m3);
        const float v1 = funmap(M1);
        const float v2 = funmap(M2);
        const float v3 = funmap(M3);

        const float t_e = expf(v2 - v1);
        const float g1 = 1.0f / (1.0f + t_e);
        const float g2 = t_e / (1.0f + t_e);

        // prob/load: one expert per lane (parallel erf, conflict-free atomics)
        if (lane < EE) {
            const float thr = (ne > v3) ? v3 : v2;
            atomicAdd(&s_load[lane], phif((ce - thr) / se));
        }
        if (lane == 0) {
            atomicAdd(&s_imp[i1], g1);
            if (g2 > 0.0f) atomicAdd(&s_imp[i2], g2);
        }

        // ---- Givens + distance, ONLY for experts i1 and i2 (50 pairs) ----
        const float* rd = rel_diag + (size_t)q1 * DD;
        const float* rh = entity + (size_t)t2 * DD;
        float dA = 0.0f, dB = 0.0f;    // d2[i1], d2[i2]

        {   // item 1: lanes 0..24 -> expert i1, lanes 25..31 -> expert i2
            const bool sel = lane < 25;
            const int e = sel ? i1 : i2;
            const int p = sel ? lane : lane - 25;
            const float2 r2 = __ldg((const float2*)(rd + e * RANKK) + p);
            const float2 h2v = __ldg((const float2*)(rh + e * RANKK) + p);
            const float inv = rsqrtf(fmaxf(r2.x * r2.x + r2.y * r2.y, 1e-30f));
            const float c0 = r2.x * inv, c1 = r2.y * inv;
            const float2 x01 = *(const float2*)&sxw[XOFF + e * RANKK + 2 * p];
            const float2 rl01 = *(const float2*)&sxw[XOFF + DD + e * (2 * RANKK) + 2 * p];
            const float u0 = (c0 * x01.x - c1 * x01.y) + rl01.x - h2v.x;
            const float u1 = (c1 * x01.x + c0 * x01.y) + rl01.y - h2v.y;
            const float dd = fmaf(u0, u0, u1 * u1);
            if (sel) dA += dd; else dB += dd;
        }
        if (lane < 18) {  // item 2: expert i2, p = lane+7
            const int p = lane + 7;
            const int e = i2;
            const float2 r2 = __ldg((const float2*)(rd + e * RANKK) + p);
            const float2 h2v = __ldg((const float2*)(rh + e * RANKK) + p);
            const float inv = rsqrtf(fmaxf(r2.x * r2.x + r2.y * r2.y, 1e-30f));
            const float c0 = r2.x * inv, c1 = r2.y * inv;
            const float2 x01 = *(const float2*)&sxw[XOFF + e * RANKK + 2 * p];
            const float2 rl01 = *(const float2*)&sxw[XOFF + DD + e * (2 * RANKK) + 2 * p];
            const float u0 = (c0 * x01.x - c1 * x01.y) + rl01.x - h2v.x;
            const float u1 = (c1 * x01.x + c0 * x01.y) + rl01.y - h2v.y;
            dB = fmaf(u0, u0, fmaf(u1, u1, dB));
        }
        #pragma unroll
        for (int off = 16; off > 0; off >>= 1) {
            dA += __shfl_xor_sync(0xffffffffu, dA, off);
            dB += __shfl_xor_sync(0xffffffffu, dB, off);
        }

        // ---- score + masked logsumexp (mask = top-2 gates > 0) ----
        if (lane == 0) {
            const float cc = softplusf(c_param[q1]);
            const float bsum = bh[q0] + bt[t2];
            const float sc1 = bsum - cc * dA;
            const float sc2 = bsum - cc * dB;
            float s = expf(sc1) + (g2 > 0.0f ? expf(sc2) : 0.0f);
            if (s == 0.0f) s = 2.220446049250313e-16f;
            y_out[b] = logf(s);
        }
    }

    __syncthreads();
    if (tid < EE)       g_part[tid * NBP + blockIdx.x] = s_load[tid];
    else if (tid < 18)  g_part[tid * NBP + blockIdx.x] = s_imp[tid - 9];
    __threadfence();
    if (tid == 0) {
        const unsigned int c = atomicAdd(&g_count, 1u);
        s_is_last = (c == NB - 1) ? 1u : 0u;
    }
    __syncthreads();
    if (!s_is_last) return;

    // ---- last block: reduce 18 per-block partial vectors and emit loss ----
    for (int v = warp; v < 18; v += WPB) {
        float acc = 0.0f;
        #pragma unroll
        for (int j = 0; j < NBP / 32; j++)    // pads are zero
            acc += g_part[v * NBP + j * 32 + lane];
        #pragma unroll
        for (int off = 16; off > 0; off >>= 1)
            acc += __shfl_xor_sync(0xffffffffu, acc, off);
        if (lane == 0) totals[v] = (double)acc;
    }
    __syncthreads();
    if (tid == 0) {
        double ml = 0.0, mi = 0.0;
        for (int e = 0; e < EE; e++) { ml += totals[e]; mi += totals[9 + e]; }
        ml /= (double)EE; mi /= (double)EE;
        double vl = 0.0, vi = 0.0;
        for (int e = 0; e < EE; e++) {
            const double dl = totals[e] - ml;     vl += dl * dl;
            const double di = totals[9 + e] - mi; vi += di * di;
        }
        vl /= (double)(EE - 1); vi /= (double)(EE - 1);
        const double cvl = vl / (ml * ml + 1e-10);
        const double cvi = vi / (mi * mi + 1e-10);
        y_out[loss_idx] = (float)(0.01 * (cvi + cvl));
        g_count = 0;   // reset for next graph replay (deterministic)
    }
}

extern "C" void kernel_launch(void* const* d_in, const int* in_sizes, int n_in,
                              void* d_out, int out_size) {
    const int*   queries       = (const int*)  d_in[0];
    const int*   these_queries = (const int*)  d_in[1];
    const float* entity        = (const float*)d_in[2];
    const float* rel           = (const float*)d_in[3];
    const float* rel_diag      = (const float*)d_in[4];
    const float* bh            = (const float*)d_in[5];
    const float* bt            = (const float*)d_in[6];
    const float* c_param       = (const float*)d_in[7];
    const float* cnn_w         = (const float*)d_in[8];
    const float* cnn_b         = (const float*)d_in[9];
    const float* h2e_w         = (const float*)d_in[10];
    const float* h2e_b         = (const float*)d_in[11];
    const float* cnnn_w        = (const float*)d_in[12];
    const float* cnnn_b        = (const float*)d_in[13];
    const float* h2en_w        = (const float*)d_in[14];
    const float* h2en_b        = (const float*)d_in[15];
    const float* noise         = (const float*)d_in[16];
    float* out = (float*)d_out;

    swise_main_kernel<<<NB, 256>>>(
        queries, these_queries, entity, rel, rel_diag, bh, bt, c_param,
        cnn_w, cnn_b, h2e_w, h2e_b, cnnn_w, cnnn_b, h2en_w, h2en_b,
        noise, out, out_size - 1);
}

// round 12
// speedup vs baseline: 1.1805x; 1.0038x over previous
#include <cuda_runtime.h>
#include <math.h>

#define BB 32768
#define EE 9
#define RANKK 50
#define DD 450            // E*RANK
#define WPB 8             // warps per block
#define NB 740            // persistent grid: 148 SMs x 5 blocks
#define NBP 768           // padded partial stride (pad slots stay zero)
#define TOTW (NB * WPB)   // 5920 warps
#define XOFF 2            // head starts at sxw[2] so rel (sxw[452]) is 16B-aligned
#define XSZ 1352          // 2 + 450 + 900

// per-block partials: [v*NBP + block], v = 0..8 load, 9..17 importance
__device__ float g_part[18 * NBP];
__device__ unsigned int g_count = 0;

__device__ __forceinline__ float softplusf(float x) {
    if (x > 20.0f) return x;
    return log1pf(expf(x));
}
__device__ __forceinline__ float phif(float z) {
    return 0.5f * (1.0f + erff(z * 0.70710678118654752f));
}
__device__ __forceinline__ void cp_async8(unsigned int dst, const void* src) {
    asm volatile("cp.async.ca.shared.global [%0], [%1], 8;" :: "r"(dst), "l"(src));
}
__device__ __forceinline__ void cp_async16(unsigned int dst, const void* src) {
    asm volatile("cp.async.ca.shared.global [%0], [%1], 16;" :: "r"(dst), "l"(src));
}
__device__ __forceinline__ void cp_async_wait_all() {
    asm volatile("cp.async.commit_group;\n\tcp.async.wait_group 0;" ::: "memory");
}
// order-preserving float -> uint map (monotone): sort by unsigned compare
__device__ __forceinline__ unsigned int fmap(float f) {
    const unsigned int u = __float_as_uint(f);
    return (u & 0x80000000u) ? ~u : (u | 0x80000000u);
}
__device__ __forceinline__ float funmap(unsigned int m) {
    return (m & 0x80000000u) ? __uint_as_float(m & 0x7FFFFFFFu)
                             : __uint_as_float(~m);
}
__device__ __forceinline__ float dot4(const float a[4], float4 w) {
    float r = a[0] * w.x; r = fmaf(a[1], w.y, r);
    r = fmaf(a[2], w.z, r); return fmaf(a[3], w.w, r);
}

__global__ __launch_bounds__(256, 5) void swise_main_kernel(
    const int* __restrict__ queries, const int* __restrict__ these_queries,
    const float* __restrict__ entity, const float* __restrict__ rel,
    const float* __restrict__ rel_diag,
    const float* __restrict__ bh, const float* __restrict__ bt,
    const float* __restrict__ c_param,
    const float* __restrict__ cnn_w, const float* __restrict__ cnn_b,
    const float* __restrict__ h2e_w, const float* __restrict__ h2e_b,
    const float* __restrict__ cnnn_w, const float* __restrict__ cnnn_b,
    const float* __restrict__ h2en_w, const float* __restrict__ h2en_b,
    const float* __restrict__ noise, float* __restrict__ y_out, int loss_idx)
{
    __shared__ __align__(16) float sx[WPB][XSZ];   // x image per warp
    __shared__ float2 swcn[25];                    // interleaved conv weights
    __shared__ float sbc[2];
    __shared__ float sbeb[18];                     // [0..8]=h2e_b, [9..17]=h2en_b
    __shared__ float s_load[EE], s_imp[EE];
    __shared__ unsigned int s_is_last;
    __shared__ double totals[18];

    const int tid = threadIdx.x;
    for (int i = tid; i < 25; i += blockDim.x)
        swcn[i] = make_float2(cnn_w[i], cnnn_w[i]);
    if (tid == 0) { sbc[0] = cnn_b[0]; sbc[1] = cnnn_b[0]; }
    if (tid < EE) { sbeb[tid] = h2e_b[tid]; sbeb[9 + tid] = h2en_b[tid];
                    s_load[tid] = 0.0f; s_imp[tid] = 0.0f; }
    __syncthreads();

    const int warp = tid >> 5, lane = tid & 31;
    const int ly = lane >> 2;          // oh  (0..7)
    const int lx = lane & 3;           // ow group (0..3)
    const int f4 = (16 * ly + 4 * lx) >> 2;
    const bool lowh = (lane < 16);
    const bool isA = (lane < EE);
    const bool isB = (lane >= 16) && (lane < 16 + EE);
    const int eIdx = isB ? (lane - 16) : lane;   // expert owned (if isA||isB)
    float* sxw = sx[warp];
    const unsigned int sxw_u32 =
        (unsigned int)__cvta_generic_to_shared(sxw);
    const float4* wc4p = (const float4*)h2e_w;
    const float4* wn4p = (const float4*)h2en_w;
    const int gw = blockIdx.x * WPB + warp;

    for (int pb = gw; pb < BB / 2; pb += TOTW) {
        const int bA = 2 * pb, bB = 2 * pb + 1;
        const int q0A = queries[3 * bA], q1A = queries[3 * bA + 1];
        const int t2A = these_queries[3 * bA + 2];
        const int q0B = queries[3 * bB], q1B = queries[3 * bB + 1];
        const int t2B = these_queries[3 * bB + 2];

        __syncwarp();   // WAR: previous pair's reads of sxw done

        // ---- stage element A ----
        {
            const float2* hrow = (const float2*)(entity + (size_t)q0A * DD);
            const float4* rrow = (const float4*)(rel + (size_t)q1A * (2 * DD));
            #pragma unroll
            for (int t = 0; t < 7; t++) {
                const int i = lane + 32 * t;
                cp_async8(sxw_u32 + 4 * (XOFF + 2 * i), hrow + i);
                cp_async16(sxw_u32 + 4 * (XOFF + DD + 4 * i), rrow + i);
            }
            if (lane == 0) {
                cp_async8(sxw_u32 + 4 * (XOFF + 2 * 224), hrow + 224);
                cp_async16(sxw_u32 + 4 * (XOFF + DD + 4 * 224), rrow + 224);
            }
        }
        // noise: lane e<9 -> element A expert e; lane 16+e -> element B expert e
        float noi = 0.0f;
        if (isA)      noi = __ldg(noise + (size_t)bA * EE + lane);
        else if (isB) noi = __ldg(noise + (size_t)bB * EE + (lane - 16));
        cp_async_wait_all();
        __syncwarp();

        // ---- conv A ----
        float accAc[4] = {0.f, 0.f, 0.f, 0.f};
        float accAn[4] = {0.f, 0.f, 0.f, 0.f};
        #pragma unroll
        for (int kh = 0; kh < 5; kh++) {
            const float* rp = sxw + XOFF + (3 * ly + kh) * RANKK + 12 * lx;
            float row[14];
            #pragma unroll
            for (int j2 = 0; j2 < 7; j2++) {
                const float2 t = *(const float2*)(rp + 2 * j2);
                row[2 * j2] = t.x; row[2 * j2 + 1] = t.y;
            }
            #pragma unroll
            for (int kw = 0; kw < 5; kw++) {
                const float2 w2 = swcn[kh * 5 + kw];
                #pragma unroll
                for (int q = 0; q < 4; q++) {
                    const float xv = row[3 * q + kw];
                    accAc[q] = fmaf(xv, w2.x, accAc[q]);
                    accAn[q] = fmaf(xv, w2.y, accAn[q]);
                }
            }
        }
        #pragma unroll
        for (int q = 0; q < 4; q++) { accAc[q] += sbc[0]; accAn[q] += sbc[1]; }

        __syncwarp();   // conv A reads done before restaging

        // ---- stage element B (same buffer) ----
        {
            const float2* hrow = (const float2*)(entity + (size_t)q0B * DD);
            const float4* rrow = (const float4*)(rel + (size_t)q1B * (2 * DD));
            #pragma unroll
            for (int t = 0; t < 7; t++) {
                const int i = lane + 32 * t;
                cp_async8(sxw_u32 + 4 * (XOFF + 2 * i), hrow + i);
                cp_async16(sxw_u32 + 4 * (XOFF + DD + 4 * i), rrow + i);
            }
            if (lane == 0) {
                cp_async8(sxw_u32 + 4 * (XOFF + 2 * 224), hrow + 224);
                cp_async16(sxw_u32 + 4 * (XOFF + DD + 4 * 224), rrow + 224);
            }
        }
        cp_async_wait_all();
        __syncwarp();

        // ---- conv B ----
        float accBc[4] = {0.f, 0.f, 0.f, 0.f};
        float accBn[4] = {0.f, 0.f, 0.f, 0.f};
        #pragma unroll
        for (int kh = 0; kh < 5; kh++) {
            const float* rp = sxw + XOFF + (3 * ly + kh) * RANKK + 12 * lx;
            float row[14];
            #pragma unroll
            for (int j2 = 0; j2 < 7; j2++) {
                const float2 t = *(const float2*)(rp + 2 * j2);
                row[2 * j2] = t.x; row[2 * j2 + 1] = t.y;
            }
            #pragma unroll
            for (int kw = 0; kw < 5; kw++) {
                const float2 w2 = swcn[kh * 5 + kw];
                #pragma unroll
                for (int q = 0; q < 4; q++) {
                    const float xv = row[3 * q + kw];
                    accBc[q] = fmaf(xv, w2.x, accBc[q]);
                    accBn[q] = fmaf(xv, w2.y, accBn[q]);
                }
            }
        }
        #pragma unroll
        for (int q = 0; q < 4; q++) { accBc[q] += sbc[0]; accBn[q] += sbc[1]; }

        // ---- joint linear: one weight load serves both elements ----
        float ce = 0.0f, nr = 0.0f;   // lane e<9: A's; lane 16+e: B's
        #pragma unroll
        for (int e = 0; e < EE; e++) {
            const float4 wc4 = __ldg(wc4p + e * 32 + f4);
            const float4 wn4 = __ldg(wn4p + e * 32 + f4);
            const float cA = dot4(accAc, wc4), nA = dot4(accAn, wn4);
            const float cB = dot4(accBc, wc4), nB = dot4(accBn, wn4);
            // route: A-sums -> low half, B-sums -> high half
            const float ocA = __shfl_xor_sync(0xffffffffu, cA, 16);
            const float onA = __shfl_xor_sync(0xffffffffu, nA, 16);
            const float ocB = __shfl_xor_sync(0xffffffffu, cB, 16);
            const float onB = __shfl_xor_sync(0xffffffffu, nB, 16);
            float u = lowh ? (cA + ocA) : (cB + ocB);
            float v = lowh ? (nA + onA) : (nB + onB);
            #pragma unroll
            for (int off = 8; off > 0; off >>= 1) {
                u += __shfl_xor_sync(0xffffffffu, u, off);
                v += __shfl_xor_sync(0xffffffffu, v, off);
            }
            if (lane == e)      { ce = u; nr = v; }
            if (lane == 16 + e) { ce = u; nr = v; }
        }

        // ---- gating: A on lanes 0..8, B on lanes 16..24 ----
        float se = 1.0f, ne = 0.0f;
        unsigned int m = 0u;
        if (isA || isB) {
            ce += sbeb[eIdx];
            se = softplusf(nr + sbeb[9 + eIdx]) + 0.01f;
            ne = fmaf(noi, se, ce);
            m = fmap(ne);
        }
        // top-3 A
        const unsigned int mA = isA ? m : 0u;
        const unsigned int M1A = __reduce_max_sync(0xffffffffu, mA);
        const int i1A = __ffs(__ballot_sync(0xffffffffu, isA && mA == M1A)) - 1;
        const unsigned int mA2 = (lane == i1A) ? 0u : mA;
        const unsigned int M2A = __reduce_max_sync(0xffffffffu, mA2);
        const int i2A = __ffs(__ballot_sync(0xffffffffu, isA && lane != i1A && mA2 == M2A)) - 1;
        const unsigned int mA3 = (lane == i2A) ? 0u : mA2;
        const unsigned int M3A = __reduce_max_sync(0xffffffffu, mA3);
        const float v1A = funmap(M1A), v2A = funmap(M2A), v3A = funmap(M3A);
        // top-3 B
        const unsigned int mB = isB ? m : 0u;
        const unsigned int M1B = __reduce_max_sync(0xffffffffu, mB);
        const int l1B = __ffs(__ballot_sync(0xffffffffu, isB && mB == M1B)) - 1;
        const unsigned int mB2 = (lane == l1B) ? 0u : mB;
        const unsigned int M2B = __reduce_max_sync(0xffffffffu, mB2);
        const int l2B = __ffs(__ballot_sync(0xffffffffu, isB && lane != l1B && mB2 == M2B)) - 1;
        const unsigned int mB3 = (lane == l2B) ? 0u : mB2;
        const unsigned int M3B = __reduce_max_sync(0xffffffffu, mB3);
        const float v1B = funmap(M1B), v2B = funmap(M2B), v3B = funmap(M3B);
        const int e1B = l1B - 16, e2B = l2B - 16;

        // load/prob atomics (both elements, conflict ≤2-way per address)
        if (isA || isB) {
            const float v3s = isA ? v3A : v3B;
            const float v2s = isA ? v2A : v2B;
            const float thr = (ne > v3s) ? v3s : v2s;
            atomicAdd(&s_load[eIdx], phif((ce - thr) / se));
        }
        const float tA = expf(v2A - v1A);
        const float g1A = 1.0f / (1.0f + tA), g2A = tA / (1.0f + tA);
        const float tB = expf(v2B - v1B);
        const float g1B = 1.0f / (1.0f + tB), g2B = tB / (1.0f + tB);
        if (lane == 0) {
            atomicAdd(&s_imp[i1A], g1A);
            if (g2A > 0.0f) atomicAdd(&s_imp[i2A], g2A);
        }
        if (lane == 1) {
            atomicAdd(&s_imp[e1B], g1B);
            if (g2B > 0.0f) atomicAdd(&s_imp[e2B], g2B);
        }

        // ---- Givens A: x-values from GLOBAL (sx now holds B) ----
        {
            const float* rd = rel_diag + (size_t)q1A * DD;
            const float* rh = entity + (size_t)t2A * DD;
            const float* hx = entity + (size_t)q0A * DD;
            const float* rl = rel + (size_t)q1A * (2 * DD);
            float d1 = 0.0f, d2 = 0.0f;
            {
                const bool sel = lane < 25;
                const int e = sel ? i1A : i2A;
                const int p = sel ? lane : lane - 25;
                const float2 r2 = __ldg((const float2*)(rd + e * RANKK) + p);
                const float2 h2v = __ldg((const float2*)(rh + e * RANKK) + p);
                const float2 x01 = __ldg((const float2*)(hx + e * RANKK) + p);
                const float2 rl01 = __ldg((const float2*)(rl + e * 2 * RANKK) + p);
                const float inv = rsqrtf(fmaxf(r2.x * r2.x + r2.y * r2.y, 1e-30f));
                const float c0 = r2.x * inv, c1 = r2.y * inv;
                const float u0 = (c0 * x01.x - c1 * x01.y) + rl01.x - h2v.x;
                const float u1 = (c1 * x01.x + c0 * x01.y) + rl01.y - h2v.y;
                const float dd = fmaf(u0, u0, u1 * u1);
                if (sel) d1 += dd; else d2 += dd;
            }
            if (lane < 18) {
                const int p = lane + 7, e = i2A;
                const float2 r2 = __ldg((const float2*)(rd + e * RANKK) + p);
                const float2 h2v = __ldg((const float2*)(rh + e * RANKK) + p);
                const float2 x01 = __ldg((const float2*)(hx + e * RANKK) + p);
                const float2 rl01 = __ldg((const float2*)(rl + e * 2 * RANKK) + p);
                const float inv = rsqrtf(fmaxf(r2.x * r2.x + r2.y * r2.y, 1e-30f));
                const float c0 = r2.x * inv, c1 = r2.y * inv;
                const float u0 = (c0 * x01.x - c1 * x01.y) + rl01.x - h2v.x;
                const float u1 = (c1 * x01.x + c0 * x01.y) + rl01.y - h2v.y;
                d2 = fmaf(u0, u0, fmaf(u1, u1, d2));
            }
            #pragma unroll
            for (int off = 16; off > 0; off >>= 1) {
                d1 += __shfl_xor_sync(0xffffffffu, d1, off);
                d2 += __shfl_xor_sync(0xffffffffu, d2, off);
            }
            if (lane == 0) {
                const float cc = softplusf(c_param[q1A]);
                const float bsum = bh[q0A] + bt[t2A];
                float s = expf(bsum - cc * d1)
                        + (g2A > 0.0f ? expf(bsum - cc * d2) : 0.0f);
                if (s == 0.0f) s = 2.220446049250313e-16f;
                y_out[bA] = logf(s);
            }
        }

        // ---- Givens B: x-values from smem (B's image resident) ----
        {
            const float* rd = rel_diag + (size_t)q1B * DD;
            const float* rh = entity + (size_t)t2B * DD;
            float d1 = 0.0f, d2 = 0.0f;
            {
                const bool sel = lane < 25;
                const int e = sel ? e1B : e2B;
                const int p = sel ? lane : lane - 25;
                const float2 r2 = __ldg((const float2*)(rd + e * RANKK) + p);
                const float2 h2v = __ldg((const float2*)(rh + e * RANKK) + p);
                const float2 x01 = *(const float2*)&sxw[XOFF + e * RANKK + 2 * p];
                const float2 rl01 = *(const float2*)&sxw[XOFF + DD + e * (2 * RANKK) + 2 * p];
                const float inv = rsqrtf(fmaxf(r2.x * r2.x + r2.y * r2.y, 1e-30f));
                const float c0 = r2.x * inv, c1 = r2.y * inv;
                const float u0 = (c0 * x01.x - c1 * x01.y) + rl01.x - h2v.x;
                const float u1 = (c1 * x01.x + c0 * x01.y) + rl01.y - h2v.y;
                const float dd = fmaf(u0, u0, u1 * u1);
                if (sel) d1 += dd; else d2 += dd;
            }
            if (lane < 18) {
                const int p = lane + 7, e = e2B;
                const float2 r2 = __ldg((const float2*)(rd + e * RANKK) + p);
                const float2 h2v = __ldg((const float2*)(rh + e * RANKK) + p);
                const float2 x01 = *(const float2*)&sxw[XOFF + e * RANKK + 2 * p];
                const float2 rl01 = *(const float2*)&sxw[XOFF + DD + e * (2 * RANKK) + 2 * p];
                const float inv = rsqrtf(fmaxf(r2.x * r2.x + r2.y * r2.y, 1e-30f));
                const float c0 = r2.x * inv, c1 = r2.y * inv;
                const float u0 = (c0 * x01.x - c1 * x01.y) + rl01.x - h2v.x;
                const float u1 = (c1 * x01.x + c0 * x01.y) + rl01.y - h2v.y;
                d2 = fmaf(u0, u0, fmaf(u1, u1, d2));
            }
            #pragma unroll
            for (int off = 16; off > 0; off >>= 1) {
                d1 += __shfl_xor_sync(0xffffffffu, d1, off);
                d2 += __shfl_xor_sync(0xffffffffu, d2, off);
            }
            if (lane == 0) {
                const float cc = softplusf(c_param[q1B]);
                const float bsum = bh[q0B] + bt[t2B];
                float s = expf(bsum - cc * d1)
                        + (g2B > 0.0f ? expf(bsum - cc * d2) : 0.0f);
                if (s == 0.0f) s = 2.220446049250313e-16f;
                y_out[bB] = logf(s);
            }
        }
    }

    __syncthreads();
    if (tid < EE)       g_part[tid * NBP + blockIdx.x] = s_load[tid];
    else if (tid < 18)  g_part[tid * NBP + blockIdx.x] = s_imp[tid - 9];
    __threadfence();
    if (tid == 0) {
        const unsigned int c = atomicAdd(&g_count, 1u);
        s_is_last = (c == NB - 1) ? 1u : 0u;
    }
    __syncthreads();
    if (!s_is_last) return;

    // ---- last block: reduce 18 per-block partial vectors and emit loss ----
    for (int v = warp; v < 18; v += WPB) {
        float acc = 0.0f;
        #pragma unroll
        for (int j = 0; j < NBP / 32; j++)    // pads are zero
            acc += g_part[v * NBP + j * 32 + lane];
        #pragma unroll
        for (int off = 16; off > 0; off >>= 1)
            acc += __shfl_xor_sync(0xffffffffu, acc, off);
        if (lane == 0) totals[v] = (double)acc;
    }
    __syncthreads();
    if (tid == 0) {
        double ml = 0.0, mi = 0.0;
        for (int e = 0; e < EE; e++) { ml += totals[e]; mi += totals[9 + e]; }
        ml /= (double)EE; mi /= (double)EE;
        double vl = 0.0, vi = 0.0;
        for (int e = 0; e < EE; e++) {
            const double dl = totals[e] - ml;     vl += dl * dl;
            const double di = totals[9 + e] - mi; vi += di * di;
        }
        vl /= (double)(EE - 1); vi /= (double)(EE - 1);
        const double cvl = vl / (ml * ml + 1e-10);
        const double cvi = vi / (mi * mi + 1e-10);
        y_out[loss_idx] = (float)(0.01 * (cvi + cvl));
        g_count = 0;   // reset for next graph replay (deterministic)
    }
}

extern "C" void kernel_launch(void* const* d_in, const int* in_sizes, int n_in,
                              void* d_out, int out_size) {
    const int*   queries       = (const int*)  d_in[0];
    const int*   these_queries = (const int*)  d_in[1];
    const float* entity        = (const float*)d_in[2];
    const float* rel           = (const float*)d_in[3];
    const float* rel_diag      = (const float*)d_in[4];
    const float* bh            = (const float*)d_in[5];
    const float* bt            = (const float*)d_in[6];
    const float* c_param       = (const float*)d_in[7];
    const float* cnn_w         = (const float*)d_in[8];
    const float* cnn_b         = (const float*)d_in[9];
    const float* h2e_w         = (const float*)d_in[10];
    const float* h2e_b         = (const float*)d_in[11];
    const float* cnnn_w        = (const float*)d_in[12];
    const float* cnnn_b        = (const float*)d_in[13];
    const float* h2en_w        = (const float*)d_in[14];
    const float* h2en_b        = (const float*)d_in[15];
    const float* noise         = (const float*)d_in[16];
    float* out = (float*)d_out;

    swise_main_kernel<<<NB, 256>>>(
        queries, these_queries, entity, rel, rel_diag, bh, bt, c_param,
        cnn_w, cnn_b, h2e_w, h2e_b, cnnn_w, cnnn_b, h2en_w, h2en_b,
        noise, out, out_size - 1);
}